// round 3
// baseline (speedup 1.0000x reference)
#include <cuda_runtime.h>
#include <cuda_bf16.h>
#include <cstdint>

#define N_NODES 100000
#define N_EDGES 1600000
#define IN_DIM 128
#define EDGE_DIM 64
#define HD 64
#define OUT_DIM 8
#define TILE_E 64
#define QKV_NODES 16
#define PITCH_T 68     // seaT row pitch in floats (17 * float4)

// ---------------- scratch ---------------------------------------------------
__device__ float g_Q[(size_t)N_NODES * HD];
__device__ float g_K[(size_t)N_NODES * HD];
__device__ float g_V[(size_t)N_NODES * HD];
__device__ float g_sum[(size_t)N_NODES * OUT_DIM];
__device__ int   g_cnt[N_NODES];
__device__ int   g_i64flag;

// ---------------- zero accumulators ----------------------------------------
__global__ void zero_kernel() {
    int i = blockIdx.x * blockDim.x + threadIdx.x;
    if (i < N_NODES * OUT_DIM) g_sum[i] = 0.f;
    if (i < N_NODES) g_cnt[i] = 0;
}

// ---------------- int32 vs int64 edge_index detection -----------------------
__global__ void detect_kernel(const void* ei) {
    if (threadIdx.x == 0 && blockIdx.x == 0) {
        const unsigned long long* p = (const unsigned long long*)ei;
        int is64 = 1;
        for (int i = 0; i < 64; i++) {
            if (p[i] >= (unsigned long long)N_NODES) { is64 = 0; break; }
        }
        g_i64flag = is64;
    }
}

// ---------------- QKV projection --------------------------------------------
// 16 nodes per block, 192 threads: t<64 -> Q col, <128 -> K col, else V col.
// W element loaded once per 16 nodes (register reuse) -> LDG issue /16.
__global__ __launch_bounds__(192) void qkv_kernel(
    const float* __restrict__ x,
    const float* __restrict__ Wq, const float* __restrict__ bq,
    const float* __restrict__ Wk, const float* __restrict__ bk,
    const float* __restrict__ Wv, const float* __restrict__ bv)
{
    __shared__ float xs[QKV_NODES][IN_DIM];
    const int nb = blockIdx.x * QKV_NODES;
    const int t = threadIdx.x;

    for (int i = t; i < QKV_NODES * (IN_DIM / 4); i += 192) {
        int n = i >> 5, kk = i & 31;
        *(float4*)&xs[n][kk * 4] =
            *(const float4*)&x[(size_t)(nb + n) * IN_DIM + kk * 4];
    }
    __syncthreads();

    const int m = t >> 6, c = t & 63;
    const float* W = (m == 0) ? Wq : (m == 1) ? Wk : Wv;
    const float* b = (m == 0) ? bq : (m == 1) ? bk : bv;

    float acc[QKV_NODES];
#pragma unroll
    for (int n = 0; n < QKV_NODES; n++) acc[n] = 0.f;

#pragma unroll 2
    for (int k = 0; k < IN_DIM; k += 4) {
        float w0 = W[(k + 0) * HD + c];
        float w1 = W[(k + 1) * HD + c];
        float w2 = W[(k + 2) * HD + c];
        float w3 = W[(k + 3) * HD + c];
#pragma unroll
        for (int n = 0; n < QKV_NODES; n++) {
            float4 xv = *(const float4*)&xs[n][k];
            acc[n] = fmaf(xv.x, w0,
                     fmaf(xv.y, w1,
                     fmaf(xv.z, w2,
                     fmaf(xv.w, w3, acc[n]))));
        }
    }
    const float bc = b[c];
    float* dstp = (m == 0) ? g_Q : (m == 1) ? g_K : g_V;
#pragma unroll
    for (int n = 0; n < QKV_NODES; n++)
        dstp[(size_t)(nb + n) * HD + c] = acc[n] + bc;
}

// ---------------- per-edge kernel -------------------------------------------
// block = 128 threads, tile = 64 edges. thread (eg = t>>3, h = t&7):
// owns edges eg*4..eg*4+3, head h (8 columns).
__global__ __launch_bounds__(128) void edge_kernel(
    const float* __restrict__ edge_attr,
    const float* __restrict__ We, const float* __restrict__ be,
    const float* __restrict__ Wo,
    const void* __restrict__ ei)
{
    __shared__ float4 sWa[EDGE_DIM * 8];   // [k][h]: We[k][h*8+0..3]   (conflict-free)
    __shared__ float4 sWb[EDGE_DIM * 8];   // [k][h]: We[k][h*8+4..7]
    __shared__ float  sWo[HD * 9];         // pitch 9
    __shared__ float  sbe[HD];
    __shared__ float  seaT[EDGE_DIM * PITCH_T]; // transposed [k][e], XOR-swizzled

    const int t = threadIdx.x;
    const int h = t & 7;
    const int eg = t >> 3;
    const int ebase = eg * 4;
    const int is64 = g_i64flag;

    for (int i = t; i < EDGE_DIM * 8; i += 128) {
        int k = i >> 3, hh = i & 7;
        sWa[i] = *(const float4*)&We[k * HD + hh * 8];
        sWb[i] = *(const float4*)&We[k * HD + hh * 8 + 4];
    }
    for (int i = t; i < HD * OUT_DIM; i += 128) sWo[(i >> 3) * 9 + (i & 7)] = Wo[i];
    if (t < HD) sbe[t] = be[t];
    __syncthreads();

    const int ntiles = N_EDGES / TILE_E;
    for (int tile = blockIdx.x; tile < ntiles; tile += gridDim.x) {
        const int e0 = tile * TILE_E;

        // ---- per-thread edge indices (no smem, issued first) ----
        int src[4], dst[4];
        if (is64) {
            const longlong2* ps = (const longlong2*)((const long long*)ei + (e0 + ebase));
            const longlong2* pd = (const longlong2*)((const long long*)ei + N_EDGES + (e0 + ebase));
            longlong2 s01 = ps[0], s23 = ps[1], d01 = pd[0], d23 = pd[1];
            src[0] = (int)s01.x; src[1] = (int)s01.y; src[2] = (int)s23.x; src[3] = (int)s23.y;
            dst[0] = (int)d01.x; dst[1] = (int)d01.y; dst[2] = (int)d23.x; dst[3] = (int)d23.y;
        } else {
            int4 s = *(const int4*)((const int*)ei + (e0 + ebase));
            int4 d = *(const int4*)((const int*)ei + N_EDGES + (e0 + ebase));
            src[0] = s.x; src[1] = s.y; src[2] = s.z; src[3] = s.w;
            dst[0] = d.x; dst[1] = d.y; dst[2] = d.z; dst[3] = d.w;
        }

        // ---- issue Q/K gathers early (latency hidden behind staging) ----
        float4 q0[4], q1[4], k0[4], k1[4];
#pragma unroll
        for (int i = 0; i < 4; i++) {
            const float4* qp = (const float4*)(g_Q + (size_t)src[i] * HD + h * 8);
            const float4* kp = (const float4*)(g_K + (size_t)dst[i] * HD + h * 8);
            q0[i] = qp[0]; q1[i] = qp[1];
            k0[i] = kp[0]; k1[i] = kp[1];
        }

        // ---- stage edge_attr tile, transposed + swizzled ----
        // i bits: [2:0]=k4lo, [8:3]=e, [9]=k4hi
        for (int i = t; i < TILE_E * 16; i += 128) {
            int k4 = (i & 7) | ((i >> 6) & 8);
            int e = (i >> 3) & 63;
            float4 v = *(const float4*)&edge_attr[(size_t)(e0 + e) * EDGE_DIM + k4 * 4];
            int col = e ^ ((k4 & 7) << 2);
            int base = k4 * 4;
            seaT[(base + 0) * PITCH_T + col] = v.x;
            seaT[(base + 1) * PITCH_T + col] = v.y;
            seaT[(base + 2) * PITCH_T + col] = v.z;
            seaT[(base + 3) * PITCH_T + col] = v.w;
        }
        __syncthreads();

        // ---- consume Q/K into scalars (frees 64 regs before GEMM) ----
        float qk[4];
#pragma unroll
        for (int i = 0; i < 4; i++) {
            qk[i] = q0[i].x * k0[i].x + q0[i].y * k0[i].y
                  + q0[i].z * k0[i].z + q0[i].w * k0[i].w
                  + q1[i].x * k1[i].x + q1[i].y * k1[i].y
                  + q1[i].z * k1[i].z + q1[i].w * k1[i].w;
        }

        // ---- E-projection GEMM: acc[4 edges][8 cols of head h] ----
        float acc[4][8];
#pragma unroll
        for (int i = 0; i < 4; i++)
#pragma unroll
            for (int j = 0; j < 8; j++) acc[i][j] = 0.f;

#pragma unroll 8
        for (int k = 0; k < EDGE_DIM; k++) {
            float4 bA = sWa[k * 8 + h];
            float4 bB = sWb[k * 8 + h];
            int col = ebase ^ (((k >> 2) & 7) << 2);
            float4 a = *(const float4*)&seaT[k * PITCH_T + col];
            float av[4] = {a.x, a.y, a.z, a.w};
#pragma unroll
            for (int i = 0; i < 4; i++) {
                acc[i][0] = fmaf(av[i], bA.x, acc[i][0]);
                acc[i][1] = fmaf(av[i], bA.y, acc[i][1]);
                acc[i][2] = fmaf(av[i], bA.z, acc[i][2]);
                acc[i][3] = fmaf(av[i], bA.w, acc[i][3]);
                acc[i][4] = fmaf(av[i], bB.x, acc[i][4]);
                acc[i][5] = fmaf(av[i], bB.y, acc[i][5]);
                acc[i][6] = fmaf(av[i], bB.z, acc[i][6]);
                acc[i][7] = fmaf(av[i], bB.w, acc[i][7]);
            }
        }
        __syncthreads();   // seaT consumed; next tile may restage

        // ---- issue V gathers now (used ~200 cyc later) ----
        float4 v0[4], v1[4];
#pragma unroll
        for (int i = 0; i < 4; i++) {
            const float4* vp = (const float4*)(g_V + (size_t)dst[i] * HD + h * 8);
            v0[i] = vp[0]; v1[i] = vp[1];
        }

        // ---- scores + softmax over heads ----
        const float inv_sqrt_d = 0.35355339059327373f;
        float wgt[4];
#pragma unroll
        for (int i = 0; i < 4; i++) {
            float s = qk[i];
#pragma unroll
            for (int d = 0; d < 8; d++) {
                float v = acc[i][d] + sbe[h * 8 + d];
                s = fmaf(v, v, s);
            }
            s *= inv_sqrt_d;
            float m = s;
            m = fmaxf(m, __shfl_xor_sync(0xffffffffu, m, 1));
            m = fmaxf(m, __shfl_xor_sync(0xffffffffu, m, 2));
            m = fmaxf(m, __shfl_xor_sync(0xffffffffu, m, 4));
            float ex = __expf(s - m);
            float sum = ex;
            sum += __shfl_xor_sync(0xffffffffu, sum, 1);
            sum += __shfl_xor_sync(0xffffffffu, sum, 2);
            sum += __shfl_xor_sync(0xffffffffu, sum, 4);
            wgt[i] = ex / sum;
        }

        // ---- out = (wgt*V) @ Wo, reduce-scatter over 8 head lanes ----
#pragma unroll
        for (int i = 0; i < 4; i++) {
            float w = wgt[i];
            float z0 = v0[i].x * w, z1 = v0[i].y * w, z2 = v0[i].z * w, z3 = v0[i].w * w;
            float z4 = v1[i].x * w, z5 = v1[i].y * w, z6 = v1[i].z * w, z7 = v1[i].w * w;
            float p[8];
#pragma unroll
            for (int j = 0; j < 8; j++) {
                const float* wrow = &sWo[(h * 8) * 9 + j];
                float a2;
                a2 = fmaf(z0, wrow[0 * 9], 0.f);
                a2 = fmaf(z1, wrow[1 * 9], a2);
                a2 = fmaf(z2, wrow[2 * 9], a2);
                a2 = fmaf(z3, wrow[3 * 9], a2);
                a2 = fmaf(z4, wrow[4 * 9], a2);
                a2 = fmaf(z5, wrow[5 * 9], a2);
                a2 = fmaf(z6, wrow[6 * 9], a2);
                a2 = fmaf(z7, wrow[7 * 9], a2);
                p[j] = a2;
            }
            // reduce-scatter: lane h ends with sum over lanes of p[h] (7 shuffles)
            bool hi4 = (h & 4) != 0;
            float t0 = hi4 ? p[0] : p[4];
            float t1 = hi4 ? p[1] : p[5];
            float t2 = hi4 ? p[2] : p[6];
            float t3 = hi4 ? p[3] : p[7];
            t0 = __shfl_xor_sync(0xffffffffu, t0, 4);
            t1 = __shfl_xor_sync(0xffffffffu, t1, 4);
            t2 = __shfl_xor_sync(0xffffffffu, t2, 4);
            t3 = __shfl_xor_sync(0xffffffffu, t3, 4);
            float q0r = (hi4 ? p[4] : p[0]) + t0;
            float q1r = (hi4 ? p[5] : p[1]) + t1;
            float q2r = (hi4 ? p[6] : p[2]) + t2;
            float q3r = (hi4 ? p[7] : p[3]) + t3;
            bool hi2 = (h & 2) != 0;
            float u0 = hi2 ? q0r : q2r;
            float u1 = hi2 ? q1r : q3r;
            u0 = __shfl_xor_sync(0xffffffffu, u0, 2);
            u1 = __shfl_xor_sync(0xffffffffu, u1, 2);
            float r0 = (hi2 ? q2r : q0r) + u0;
            float r1 = (hi2 ? q3r : q1r) + u1;
            bool hi1 = (h & 1) != 0;
            float w0s = hi1 ? r0 : r1;
            w0s = __shfl_xor_sync(0xffffffffu, w0s, 1);
            float res = (hi1 ? r1 : r0) + w0s;

            atomicAdd(&g_sum[(size_t)src[i] * OUT_DIM + h], res);
            if (h == 0) atomicAdd(&g_cnt[src[i]], 1);
        }
    }
}

// ---------------- finalize: mean + bias --------------------------------------
__global__ void finalize_kernel(float* __restrict__ out, const float* __restrict__ bo) {
    int i = blockIdx.x * blockDim.x + threadIdx.x;
    if (i < N_NODES * OUT_DIM) {
        int n = i >> 3, j = i & 7;
        int c = g_cnt[n];
        float r = 0.f;
        if (c > 0) r = g_sum[i] / (float)c + bo[j];
        out[i] = r;
    }
}

// ---------------- launcher ----------------------------------------------------
extern "C" void kernel_launch(void* const* d_in, const int* in_sizes, int n_in,
                              void* d_out, int out_size)
{
    const float* x  = (const float*)d_in[0];
    const float* ea = (const float*)d_in[1];
    const float* Wq = (const float*)d_in[2];
    const float* bq = (const float*)d_in[3];
    const float* Wk = (const float*)d_in[4];
    const float* bk = (const float*)d_in[5];
    const float* Wv = (const float*)d_in[6];
    const float* bv = (const float*)d_in[7];
    const float* We = (const float*)d_in[8];
    const float* be = (const float*)d_in[9];
    const float* Wo = (const float*)d_in[10];
    const float* bo = (const float*)d_in[11];
    const void*  ei = d_in[12];
    float* out = (float*)d_out;

    zero_kernel<<<(N_NODES * OUT_DIM + 255) / 256, 256>>>();
    detect_kernel<<<1, 32>>>(ei);
    qkv_kernel<<<N_NODES / QKV_NODES, 192>>>(x, Wq, bq, Wk, bk, Wv, bv);
    edge_kernel<<<1184, 128>>>(ea, We, be, Wo, ei);
    finalize_kernel<<<(N_NODES * OUT_DIM + 255) / 256, 256>>>(out, bo);
}

// round 4
// speedup vs baseline: 1.0628x; 1.0628x over previous
#include <cuda_runtime.h>
#include <cuda_bf16.h>
#include <cstdint>

#define N_NODES 100000
#define N_EDGES 1600000
#define IN_DIM 128
#define EDGE_DIM 64
#define HD 64
#define OUT_DIM 8
#define TILE_E 64
#define QKV_NODES 16
#define PITCH_T 68

__device__ __forceinline__ unsigned long long pk2(float lo, float hi) {
    unsigned long long r;
    asm("mov.b64 %0, {%1, %2};" : "=l"(r) : "f"(lo), "f"(hi));
    return r;
}
__device__ __forceinline__ void upk2(unsigned long long v, float& lo, float& hi) {
    asm("mov.b64 {%0, %1}, %2;" : "=f"(lo), "=f"(hi) : "l"(v));
}
#define FFMA2(d, a, b) asm("fma.rn.f32x2 %0, %1, %2, %0;" : "+l"(d) : "l"(a), "l"(b))

// ---------------- scratch ----------------------------------------------------
__device__ float g_Q[(size_t)N_NODES * HD];
__device__ float g_K[(size_t)N_NODES * HD];
__device__ float g_VW[(size_t)N_NODES * HD];   // (V @ Wo) per head: [n][h][j]
__device__ float g_sum[(size_t)N_NODES * OUT_DIM];
__device__ int   g_cnt[N_NODES];
__device__ int   g_i64flag;

__global__ void zero_kernel() {
    int i = blockIdx.x * blockDim.x + threadIdx.x;
    if (i < N_NODES * OUT_DIM) g_sum[i] = 0.f;
    if (i < N_NODES) g_cnt[i] = 0;
}

__global__ void detect_kernel(const void* ei) {
    if (threadIdx.x == 0 && blockIdx.x == 0) {
        const unsigned long long* p = (const unsigned long long*)ei;
        int is64 = 1;
        for (int i = 0; i < 64; i++)
            if (p[i] >= (unsigned long long)N_NODES) { is64 = 0; break; }
        g_i64flag = is64;
    }
}

// ---------------- QKV projection + fused VW = V @ Wo (per head) --------------
__global__ __launch_bounds__(192) void qkv_kernel(
    const float* __restrict__ x,
    const float* __restrict__ Wq, const float* __restrict__ bq,
    const float* __restrict__ Wk, const float* __restrict__ bk,
    const float* __restrict__ Wv, const float* __restrict__ bv,
    const float* __restrict__ Wo)
{
    __shared__ float xs[QKV_NODES][IN_DIM];
    __shared__ float xv[QKV_NODES][HD + 1];
    __shared__ float swo[HD * 9];
    const int nb = blockIdx.x * QKV_NODES;
    const int t = threadIdx.x;

    for (int i = t; i < HD * OUT_DIM; i += 192) swo[(i >> 3) * 9 + (i & 7)] = Wo[i];
    for (int i = t; i < QKV_NODES * (IN_DIM / 4); i += 192) {
        int n = i >> 5, kk = i & 31;
        *(float4*)&xs[n][kk * 4] =
            *(const float4*)&x[(size_t)(nb + n) * IN_DIM + kk * 4];
    }
    __syncthreads();

    const int m = t >> 6, c = t & 63;
    const float* W = (m == 0) ? Wq : (m == 1) ? Wk : Wv;
    const float* b = (m == 0) ? bq : (m == 1) ? bk : bv;

    float acc[QKV_NODES];
#pragma unroll
    for (int n = 0; n < QKV_NODES; n++) acc[n] = 0.f;

#pragma unroll 2
    for (int k = 0; k < IN_DIM; k += 4) {
        float w0 = W[(k + 0) * HD + c];
        float w1 = W[(k + 1) * HD + c];
        float w2 = W[(k + 2) * HD + c];
        float w3 = W[(k + 3) * HD + c];
#pragma unroll
        for (int n = 0; n < QKV_NODES; n++) {
            float4 xvv = *(const float4*)&xs[n][k];
            acc[n] = fmaf(xvv.x, w0, fmaf(xvv.y, w1,
                     fmaf(xvv.z, w2, fmaf(xvv.w, w3, acc[n]))));
        }
    }
    const float bc = b[c];
    if (m == 2) {
#pragma unroll
        for (int n = 0; n < QKV_NODES; n++) xv[n][c] = acc[n] + bc;
    } else {
        float* dstp = (m == 0) ? g_Q : g_K;
#pragma unroll
        for (int n = 0; n < QKV_NODES; n++)
            dstp[(size_t)(nb + n) * HD + c] = acc[n] + bc;
    }
    __syncthreads();

    // VW[n][h*8+j] = sum_d V[n][h*8+d] * Wo[(h*8+d)][j]
    for (int i = t; i < QKV_NODES * HD; i += 192) {
        int n = i >> 6, cc = i & 63;
        int h8 = cc & 56, j = cc & 7;
        const float* vr = &xv[n][h8];
        const float* wr = &swo[h8 * 9 + j];
        float s = 0.f;
#pragma unroll
        for (int d = 0; d < 8; d++) s = fmaf(vr[d], wr[d * 9], s);
        g_VW[(size_t)(nb + n) * HD + cc] = s;
    }
}

// ---------------- per-edge kernel --------------------------------------------
__global__ __launch_bounds__(128) void edge_kernel(
    const float* __restrict__ edge_attr,
    const float* __restrict__ We, const float* __restrict__ be,
    const void* __restrict__ ei)
{
    __shared__ float4 sWa[EDGE_DIM * 8];   // [k][h]: cols h*8..+3
    __shared__ float4 sWb[EDGE_DIM * 8];   // [k][h]: cols h*8+4..+7
    __shared__ float  sbe[HD];
    __shared__ float  seaT[EDGE_DIM * PITCH_T];

    const int t = threadIdx.x;
    const int h = t & 7;
    const int eg = t >> 3;
    const int ebase = eg * 4;
    const int is64 = g_i64flag;

    for (int i = t; i < EDGE_DIM * 8; i += 128) {
        int k = i >> 3, hh = i & 7;
        sWa[i] = *(const float4*)&We[k * HD + hh * 8];
        sWb[i] = *(const float4*)&We[k * HD + hh * 8 + 4];
    }
    if (t < HD) sbe[t] = be[t];
    __syncthreads();

    const int ntiles = N_EDGES / TILE_E;
    for (int tile = blockIdx.x; tile < ntiles; tile += gridDim.x) {
        const int e0 = tile * TILE_E;

        int src[4], dst[4];
        if (is64) {
            const longlong2* ps = (const longlong2*)((const long long*)ei + (e0 + ebase));
            const longlong2* pd = (const longlong2*)((const long long*)ei + N_EDGES + (e0 + ebase));
            longlong2 s01 = ps[0], s23 = ps[1], d01 = pd[0], d23 = pd[1];
            src[0] = (int)s01.x; src[1] = (int)s01.y; src[2] = (int)s23.x; src[3] = (int)s23.y;
            dst[0] = (int)d01.x; dst[1] = (int)d01.y; dst[2] = (int)d23.x; dst[3] = (int)d23.y;
        } else {
            int4 s = *(const int4*)((const int*)ei + (e0 + ebase));
            int4 d = *(const int4*)((const int*)ei + N_EDGES + (e0 + ebase));
            src[0] = s.x; src[1] = s.y; src[2] = s.z; src[3] = s.w;
            dst[0] = d.x; dst[1] = d.y; dst[2] = d.z; dst[3] = d.w;
        }

        // early Q/K gathers (L2-resident)
        float4 q0[4], q1[4], k0[4], k1[4];
#pragma unroll
        for (int i = 0; i < 4; i++) {
            const float4* qp = (const float4*)(g_Q + (size_t)src[i] * HD + h * 8);
            const float4* kp = (const float4*)(g_K + (size_t)dst[i] * HD + h * 8);
            q0[i] = qp[0]; q1[i] = qp[1];
            k0[i] = kp[0]; k1[i] = kp[1];
        }

        // stage edge_attr tile transposed + swizzled
        for (int i = t; i < TILE_E * 16; i += 128) {
            int k4 = (i & 7) | ((i >> 6) & 8);
            int e = (i >> 3) & 63;
            float4 v = *(const float4*)&edge_attr[(size_t)(e0 + e) * EDGE_DIM + k4 * 4];
            int col = e ^ ((k4 & 7) << 2);
            int base = k4 * 4;
            seaT[(base + 0) * PITCH_T + col] = v.x;
            seaT[(base + 1) * PITCH_T + col] = v.y;
            seaT[(base + 2) * PITCH_T + col] = v.z;
            seaT[(base + 3) * PITCH_T + col] = v.w;
        }
        __syncthreads();

        float qk[4];
#pragma unroll
        for (int i = 0; i < 4; i++) {
            qk[i] = q0[i].x * k0[i].x + q0[i].y * k0[i].y
                  + q0[i].z * k0[i].z + q0[i].w * k0[i].w
                  + q1[i].x * k1[i].x + q1[i].y * k1[i].y
                  + q1[i].z * k1[i].z + q1[i].w * k1[i].w;
        }

        // E-projection GEMM, f32x2 packed over column pairs
        unsigned long long acc2[4][4];
#pragma unroll
        for (int i = 0; i < 4; i++)
#pragma unroll
            for (int j = 0; j < 4; j++) acc2[i][j] = 0ull;

#pragma unroll 8
        for (int k = 0; k < EDGE_DIM; k++) {
            ulonglong2 bA = *(const ulonglong2*)&sWa[k * 8 + h];  // (b0,b1),(b2,b3)
            ulonglong2 bB = *(const ulonglong2*)&sWb[k * 8 + h];  // (b4,b5),(b6,b7)
            int col = ebase ^ (((k >> 2) & 7) << 2);
            float4 a = *(const float4*)&seaT[k * PITCH_T + col];
            float av[4] = {a.x, a.y, a.z, a.w};
#pragma unroll
            for (int i = 0; i < 4; i++) {
                unsigned long long ad = pk2(av[i], av[i]);
                FFMA2(acc2[i][0], ad, bA.x);
                FFMA2(acc2[i][1], ad, bA.y);
                FFMA2(acc2[i][2], ad, bB.x);
                FFMA2(acc2[i][3], ad, bB.y);
            }
        }
        __syncthreads();

        // prefetch VW gathers
        float4 vw0[4], vw1[4];
#pragma unroll
        for (int i = 0; i < 4; i++) {
            const float4* vp = (const float4*)(g_VW + (size_t)dst[i] * HD + h * 8);
            vw0[i] = vp[0]; vw1[i] = vp[1];
        }

        const float inv_sqrt_d = 0.35355339059327373f;
#pragma unroll
        for (int i = 0; i < 4; i++) {
            float s = qk[i];
#pragma unroll
            for (int j = 0; j < 4; j++) {
                float lo, hi; upk2(acc2[i][j], lo, hi);
                float v0 = lo + sbe[h * 8 + 2 * j];
                float v1 = hi + sbe[h * 8 + 2 * j + 1];
                s = fmaf(v0, v0, s);
                s = fmaf(v1, v1, s);
            }
            s *= inv_sqrt_d;
            float m = s;
            m = fmaxf(m, __shfl_xor_sync(0xffffffffu, m, 1));
            m = fmaxf(m, __shfl_xor_sync(0xffffffffu, m, 2));
            m = fmaxf(m, __shfl_xor_sync(0xffffffffu, m, 4));
            float ex = __expf(s - m);
            float sum = ex;
            sum += __shfl_xor_sync(0xffffffffu, sum, 1);
            sum += __shfl_xor_sync(0xffffffffu, sum, 2);
            sum += __shfl_xor_sync(0xffffffffu, sum, 4);
            float wgt = ex / sum;

            // p[j] = wgt * VW[dst][h][j]; reduce over head lanes (reduce-scatter)
            float p[8] = { wgt * vw0[i].x, wgt * vw0[i].y, wgt * vw0[i].z, wgt * vw0[i].w,
                           wgt * vw1[i].x, wgt * vw1[i].y, wgt * vw1[i].z, wgt * vw1[i].w };
            bool hi4 = (h & 4) != 0;
            float t0 = hi4 ? p[0] : p[4];
            float t1 = hi4 ? p[1] : p[5];
            float t2 = hi4 ? p[2] : p[6];
            float t3 = hi4 ? p[3] : p[7];
            t0 = __shfl_xor_sync(0xffffffffu, t0, 4);
            t1 = __shfl_xor_sync(0xffffffffu, t1, 4);
            t2 = __shfl_xor_sync(0xffffffffu, t2, 4);
            t3 = __shfl_xor_sync(0xffffffffu, t3, 4);
            float q0r = (hi4 ? p[4] : p[0]) + t0;
            float q1r = (hi4 ? p[5] : p[1]) + t1;
            float q2r = (hi4 ? p[6] : p[2]) + t2;
            float q3r = (hi4 ? p[7] : p[3]) + t3;
            bool hi2 = (h & 2) != 0;
            float u0 = hi2 ? q0r : q2r;
            float u1 = hi2 ? q1r : q3r;
            u0 = __shfl_xor_sync(0xffffffffu, u0, 2);
            u1 = __shfl_xor_sync(0xffffffffu, u1, 2);
            float r0 = (hi2 ? q2r : q0r) + u0;
            float r1 = (hi2 ? q3r : q1r) + u1;
            bool hi1 = (h & 1) != 0;
            float w0s = hi1 ? r0 : r1;
            w0s = __shfl_xor_sync(0xffffffffu, w0s, 1);
            float res = (hi1 ? r1 : r0) + w0s;

            atomicAdd(&g_sum[(size_t)src[i] * OUT_DIM + h], res);
            if (h == 0) atomicAdd(&g_cnt[src[i]], 1);
        }
    }
}

__global__ void finalize_kernel(float* __restrict__ out, const float* __restrict__ bo) {
    int i = blockIdx.x * blockDim.x + threadIdx.x;
    if (i < N_NODES * OUT_DIM) {
        int n = i >> 3, j = i & 7;
        int c = g_cnt[n];
        float r = 0.f;
        if (c > 0) r = g_sum[i] / (float)c + bo[j];
        out[i] = r;
    }
}

extern "C" void kernel_launch(void* const* d_in, const int* in_sizes, int n_in,
                              void* d_out, int out_size)
{
    const float* x  = (const float*)d_in[0];
    const float* ea = (const float*)d_in[1];
    const float* Wq = (const float*)d_in[2];
    const float* bq = (const float*)d_in[3];
    const float* Wk = (const float*)d_in[4];
    const float* bk = (const float*)d_in[5];
    const float* Wv = (const float*)d_in[6];
    const float* bv = (const float*)d_in[7];
    const float* We = (const float*)d_in[8];
    const float* be = (const float*)d_in[9];
    const float* Wo = (const float*)d_in[10];
    const float* bo = (const float*)d_in[11];
    const void*  ei = d_in[12];
    float* out = (float*)d_out;

    zero_kernel<<<(N_NODES * OUT_DIM + 255) / 256, 256>>>();
    detect_kernel<<<1, 32>>>(ei);
    qkv_kernel<<<N_NODES / QKV_NODES, 192>>>(x, Wq, bq, Wk, bk, Wv, bv, Wo);
    edge_kernel<<<1184, 128>>>(ea, We, be, ei);
    finalize_kernel<<<(N_NODES * OUT_DIM + 255) / 256, 256>>>(out, bo);
}

// round 7
// speedup vs baseline: 1.6078x; 1.5128x over previous
#include <cuda_runtime.h>
#include <cuda_bf16.h>
#include <cstdint>

#define N_NODES 100000
#define N_EDGES 1600000
#define IN_DIM 128
#define EDGE_DIM 64
#define HD 64
#define OUT_DIM 8
#define TILE_E 64
#define QKV_NODES 16
#define PITCH_T 68

// ---------------- scratch ----------------------------------------------------
__device__ float g_Q[(size_t)N_NODES * HD];
__device__ float g_K[(size_t)N_NODES * HD];
__device__ float g_VW[(size_t)N_NODES * HD];   // (V @ Wo) per head: [n][h][j]
__device__ float g_sum[(size_t)N_NODES * OUT_DIM];
__device__ int   g_cnt[N_NODES];
__device__ int   g_i64flag;

__global__ void zero_kernel() {
    int i = blockIdx.x * blockDim.x + threadIdx.x;
    if (i < N_NODES * OUT_DIM) g_sum[i] = 0.f;
    if (i < N_NODES) g_cnt[i] = 0;
}

__global__ void detect_kernel(const void* ei) {
    if (threadIdx.x == 0 && blockIdx.x == 0) {
        const unsigned long long* p = (const unsigned long long*)ei;
        int is64 = 1;
        for (int i = 0; i < 64; i++)
            if (p[i] >= (unsigned long long)N_NODES) { is64 = 0; break; }
        g_i64flag = is64;
    }
}

// ---------------- QKV projection + fused VW = V @ Wo (per head) --------------
__global__ __launch_bounds__(192) void qkv_kernel(
    const float* __restrict__ x,
    const float* __restrict__ Wq, const float* __restrict__ bq,
    const float* __restrict__ Wk, const float* __restrict__ bk,
    const float* __restrict__ Wv, const float* __restrict__ bv,
    const float* __restrict__ Wo)
{
    __shared__ float xs[QKV_NODES][IN_DIM];
    __shared__ float xv[QKV_NODES][HD + 1];
    __shared__ float swo[HD * 9];
    const int nb = blockIdx.x * QKV_NODES;
    const int t = threadIdx.x;

    for (int i = t; i < HD * OUT_DIM; i += 192) swo[(i >> 3) * 9 + (i & 7)] = Wo[i];
    for (int i = t; i < QKV_NODES * (IN_DIM / 4); i += 192) {
        int n = i >> 5, kk = i & 31;
        *(float4*)&xs[n][kk * 4] =
            *(const float4*)&x[(size_t)(nb + n) * IN_DIM + kk * 4];
    }
    __syncthreads();

    const int m = t >> 6, c = t & 63;
    const float* W = (m == 0) ? Wq : (m == 1) ? Wk : Wv;
    const float* b = (m == 0) ? bq : (m == 1) ? bk : bv;

    float acc[QKV_NODES];
#pragma unroll
    for (int n = 0; n < QKV_NODES; n++) acc[n] = 0.f;

#pragma unroll 2
    for (int k = 0; k < IN_DIM; k += 4) {
        float w0 = W[(k + 0) * HD + c];
        float w1 = W[(k + 1) * HD + c];
        float w2 = W[(k + 2) * HD + c];
        float w3 = W[(k + 3) * HD + c];
#pragma unroll
        for (int n = 0; n < QKV_NODES; n++) {
            float4 xvv = *(const float4*)&xs[n][k];
            acc[n] = fmaf(xvv.x, w0, fmaf(xvv.y, w1,
                     fmaf(xvv.z, w2, fmaf(xvv.w, w3, acc[n]))));
        }
    }
    const float bc = b[c];
    if (m == 2) {
#pragma unroll
        for (int n = 0; n < QKV_NODES; n++) xv[n][c] = acc[n] + bc;
    } else {
        float* dstp = (m == 0) ? g_Q : g_K;
#pragma unroll
        for (int n = 0; n < QKV_NODES; n++)
            dstp[(size_t)(nb + n) * HD + c] = acc[n] + bc;
    }
    __syncthreads();

    // VW[n][h*8+j] = sum_d V[n][h*8+d] * Wo[(h*8+d)][j]
    for (int i = t; i < QKV_NODES * HD; i += 192) {
        int n = i >> 6, cc = i & 63;
        int h8 = cc & 56, j = cc & 7;
        const float* vr = &xv[n][h8];
        const float* wr = &swo[h8 * 9 + j];
        float s = 0.f;
#pragma unroll
        for (int d = 0; d < 8; d++) s = fmaf(vr[d], wr[d * 9], s);
        g_VW[(size_t)(nb + n) * HD + cc] = s;
    }
}

// ---------------- per-edge kernel --------------------------------------------
// 128 threads, tile = 64 edges. thread (eg = t>>3, h = t&7):
// edges eg*4..+3, head h. Proven R2 scalar-FFMA GEMM + VW epilogue.
__global__ __launch_bounds__(128) void edge_kernel(
    const float* __restrict__ edge_attr,
    const float* __restrict__ We, const float* __restrict__ be,
    const void* __restrict__ ei)
{
    __shared__ float4 sWa[EDGE_DIM * 8];   // [k][h]: We cols h*8..+3
    __shared__ float4 sWb[EDGE_DIM * 8];   // [k][h]: We cols h*8+4..+7
    __shared__ float  seaT[EDGE_DIM * PITCH_T];

    const int t = threadIdx.x;
    const int h = t & 7;
    const int eg = t >> 3;
    const int ebase = eg * 4;
    const int is64 = g_i64flag;

    for (int i = t; i < EDGE_DIM * 8; i += 128) {
        int k = i >> 3, hh = i & 7;
        sWa[i] = *(const float4*)&We[k * HD + hh * 8];
        sWb[i] = *(const float4*)&We[k * HD + hh * 8 + 4];
    }
    // this head's bias in registers (kills epilogue LDS)
    float4 be0 = *(const float4*)&be[h * 8];
    float4 be1 = *(const float4*)&be[h * 8 + 4];
    __syncthreads();

    const int ntiles = N_EDGES / TILE_E;
    for (int tile = blockIdx.x; tile < ntiles; tile += gridDim.x) {
        const int e0 = tile * TILE_E;

        int src[4], dst[4];
        if (is64) {
            const longlong2* ps = (const longlong2*)((const long long*)ei + (e0 + ebase));
            const longlong2* pd = (const longlong2*)((const long long*)ei + N_EDGES + (e0 + ebase));
            longlong2 s01 = ps[0], s23 = ps[1], d01 = pd[0], d23 = pd[1];
            src[0] = (int)s01.x; src[1] = (int)s01.y; src[2] = (int)s23.x; src[3] = (int)s23.y;
            dst[0] = (int)d01.x; dst[1] = (int)d01.y; dst[2] = (int)d23.x; dst[3] = (int)d23.y;
        } else {
            int4 s = *(const int4*)((const int*)ei + (e0 + ebase));
            int4 d = *(const int4*)((const int*)ei + N_EDGES + (e0 + ebase));
            src[0] = s.x; src[1] = s.y; src[2] = s.z; src[3] = s.w;
            dst[0] = d.x; dst[1] = d.y; dst[2] = d.z; dst[3] = d.w;
        }

        // early Q/K gathers (L2-resident)
        float4 q0[4], q1[4], k0[4], k1[4];
#pragma unroll
        for (int i = 0; i < 4; i++) {
            const float4* qp = (const float4*)(g_Q + (size_t)src[i] * HD + h * 8);
            const float4* kp = (const float4*)(g_K + (size_t)dst[i] * HD + h * 8);
            q0[i] = qp[0]; q1[i] = qp[1];
            k0[i] = kp[0]; k1[i] = kp[1];
        }

        // stage edge_attr tile transposed + swizzled
        for (int i = t; i < TILE_E * 16; i += 128) {
            int k4 = (i & 7) | ((i >> 6) & 8);
            int e = (i >> 3) & 63;
            float4 v = *(const float4*)&edge_attr[(size_t)(e0 + e) * EDGE_DIM + k4 * 4];
            int col = e ^ ((k4 & 7) << 2);
            int base = k4 * 4;
            seaT[(base + 0) * PITCH_T + col] = v.x;
            seaT[(base + 1) * PITCH_T + col] = v.y;
            seaT[(base + 2) * PITCH_T + col] = v.z;
            seaT[(base + 3) * PITCH_T + col] = v.w;
        }
        __syncthreads();

        // fold Q.K into scalars (frees regs before GEMM)
        float qk[4];
#pragma unroll
        for (int i = 0; i < 4; i++) {
            qk[i] = q0[i].x * k0[i].x + q0[i].y * k0[i].y
                  + q0[i].z * k0[i].z + q0[i].w * k0[i].w
                  + q1[i].x * k1[i].x + q1[i].y * k1[i].y
                  + q1[i].z * k1[i].z + q1[i].w * k1[i].w;
        }

        // E-projection GEMM: acc[4 edges][8 cols of head h]  (scalar FFMA)
        float acc[4][8];
#pragma unroll
        for (int i = 0; i < 4; i++)
#pragma unroll
            for (int j = 0; j < 8; j++) acc[i][j] = 0.f;

#pragma unroll 8
        for (int k = 0; k < EDGE_DIM; k++) {
            float4 bA = sWa[k * 8 + h];
            float4 bB = sWb[k * 8 + h];
            int col = ebase ^ (((k >> 2) & 7) << 2);
            float4 a = *(const float4*)&seaT[k * PITCH_T + col];
            float av[4] = {a.x, a.y, a.z, a.w};
#pragma unroll
            for (int i = 0; i < 4; i++) {
                acc[i][0] = fmaf(av[i], bA.x, acc[i][0]);
                acc[i][1] = fmaf(av[i], bA.y, acc[i][1]);
                acc[i][2] = fmaf(av[i], bA.z, acc[i][2]);
                acc[i][3] = fmaf(av[i], bA.w, acc[i][3]);
                acc[i][4] = fmaf(av[i], bB.x, acc[i][4]);
                acc[i][5] = fmaf(av[i], bB.y, acc[i][5]);
                acc[i][6] = fmaf(av[i], bB.z, acc[i][6]);
                acc[i][7] = fmaf(av[i], bB.w, acc[i][7]);
            }
        }
        __syncthreads();

        // prefetch VW gathers (consumed ~150 cyc later)
        float4 vw0[4], vw1[4];
#pragma unroll
        for (int i = 0; i < 4; i++) {
            const float4* vp = (const float4*)(g_VW + (size_t)dst[i] * HD + h * 8);
            vw0[i] = vp[0]; vw1[i] = vp[1];
        }

        const float inv_sqrt_d = 0.35355339059327373f;
#pragma unroll
        for (int i = 0; i < 4; i++) {
            // scores: qk + ||E + be||^2
            float s = qk[i];
            float v;
            v = acc[i][0] + be0.x; s = fmaf(v, v, s);
            v = acc[i][1] + be0.y; s = fmaf(v, v, s);
            v = acc[i][2] + be0.z; s = fmaf(v, v, s);
            v = acc[i][3] + be0.w; s = fmaf(v, v, s);
            v = acc[i][4] + be1.x; s = fmaf(v, v, s);
            v = acc[i][5] + be1.y; s = fmaf(v, v, s);
            v = acc[i][6] + be1.z; s = fmaf(v, v, s);
            v = acc[i][7] + be1.w; s = fmaf(v, v, s);
            s *= inv_sqrt_d;

            // softmax over the 8 head lanes
            float m = s;
            m = fmaxf(m, __shfl_xor_sync(0xffffffffu, m, 1));
            m = fmaxf(m, __shfl_xor_sync(0xffffffffu, m, 2));
            m = fmaxf(m, __shfl_xor_sync(0xffffffffu, m, 4));
            float ex = __expf(s - m);
            float sum = ex;
            sum += __shfl_xor_sync(0xffffffffu, sum, 1);
            sum += __shfl_xor_sync(0xffffffffu, sum, 2);
            sum += __shfl_xor_sync(0xffffffffu, sum, 4);
            float wgt = ex / sum;

            // p[j] = wgt * VW[dst][h][j]; reduce-scatter over 8 head lanes
            float p[8] = { wgt * vw0[i].x, wgt * vw0[i].y, wgt * vw0[i].z, wgt * vw0[i].w,
                           wgt * vw1[i].x, wgt * vw1[i].y, wgt * vw1[i].z, wgt * vw1[i].w };
            bool hi4 = (h & 4) != 0;
            float t0 = hi4 ? p[0] : p[4];
            float t1 = hi4 ? p[1] : p[5];
            float t2 = hi4 ? p[2] : p[6];
            float t3 = hi4 ? p[3] : p[7];
            t0 = __shfl_xor_sync(0xffffffffu, t0, 4);
            t1 = __shfl_xor_sync(0xffffffffu, t1, 4);
            t2 = __shfl_xor_sync(0xffffffffu, t2, 4);
            t3 = __shfl_xor_sync(0xffffffffu, t3, 4);
            float q0r = (hi4 ? p[4] : p[0]) + t0;
            float q1r = (hi4 ? p[5] : p[1]) + t1;
            float q2r = (hi4 ? p[6] : p[2]) + t2;
            float q3r = (hi4 ? p[7] : p[3]) + t3;
            bool hi2 = (h & 2) != 0;
            float u0 = hi2 ? q0r : q2r;
            float u1 = hi2 ? q1r : q3r;
            u0 = __shfl_xor_sync(0xffffffffu, u0, 2);
            u1 = __shfl_xor_sync(0xffffffffu, u1, 2);
            float r0 = (hi2 ? q2r : q0r) + u0;
            float r1 = (hi2 ? q3r : q1r) + u1;
            bool hi1 = (h & 1) != 0;
            float w0s = hi1 ? r0 : r1;
            w0s = __shfl_xor_sync(0xffffffffu, w0s, 1);
            float res = (hi1 ? r1 : r0) + w0s;

            atomicAdd(&g_sum[(size_t)src[i] * OUT_DIM + h], res);
            if (h == 0) atomicAdd(&g_cnt[src[i]], 1);
        }
    }
}

__global__ void finalize_kernel(float* __restrict__ out, const float* __restrict__ bo) {
    int i = blockIdx.x * blockDim.x + threadIdx.x;
    if (i < N_NODES * OUT_DIM) {
        int n = i >> 3, j = i & 7;
        int c = g_cnt[n];
        float r = 0.f;
        if (c > 0) r = g_sum[i] / (float)c + bo[j];
        out[i] = r;
    }
}

extern "C" void kernel_launch(void* const* d_in, const int* in_sizes, int n_in,
                              void* d_out, int out_size)
{
    const float* x  = (const float*)d_in[0];
    const float* ea = (const float*)d_in[1];
    const float* Wq = (const float*)d_in[2];
    const float* bq = (const float*)d_in[3];
    const float* Wk = (const float*)d_in[4];
    const float* bk = (const float*)d_in[5];
    const float* Wv = (const float*)d_in[6];
    const float* bv = (const float*)d_in[7];
    const float* We = (const float*)d_in[8];
    const float* be = (const float*)d_in[9];
    const float* Wo = (const float*)d_in[10];
    const float* bo = (const float*)d_in[11];
    const void*  ei = d_in[12];
    float* out = (float*)d_out;

    zero_kernel<<<(N_NODES * OUT_DIM + 255) / 256, 256>>>();
    detect_kernel<<<1, 32>>>(ei);
    qkv_kernel<<<N_NODES / QKV_NODES, 192>>>(x, Wq, bq, Wk, bk, Wv, bv, Wo);
    edge_kernel<<<1184, 128>>>(ea, We, be, ei);
    finalize_kernel<<<(N_NODES * OUT_DIM + 255) / 256, 256>>>(out, bo);
}